// round 8
// baseline (speedup 1.0000x reference)
#include <cuda_runtime.h>
#include <math.h>

#define B_    16
#define C_    128
#define HIM   32
#define WIM   32
#define NTOK  640
#define S_    256
#define EMBD  256
#define NHEAD 8
#define DH    32
#define BH    128
#define T_    640
#define NH    8
#define NB    10
#define NC    80

typedef unsigned long long u64;
// packed f32x2 helpers (sm_100+): 2 fp32 FMAs per issue slot
__device__ __forceinline__ u64 pk2(float v) {
    u64 r; asm("mov.b64 %0, {%1,%1};" : "=l"(r) : "f"(v)); return r;
}
__device__ __forceinline__ u64 ffma2(u64 a, u64 b, u64 c) {
    u64 d; asm("fma.rn.f32x2 %0, %1, %2, %3;" : "=l"(d) : "l"(a), "l"(b), "l"(c)); return d;
}
__device__ __forceinline__ float2 upk2(u64 v) {
    float2 f; asm("mov.b64 {%0,%1}, %2;" : "=f"(f.x), "=f"(f.y) : "l"(v)); return f;
}

// ---------------- scratch ----------------
__device__ float g_tokens[B_ * NTOK * S_];
__device__ float g_qk[BH * T_ * DH];
__device__ float g_v [BH * T_ * DH];
__device__ int   g_bkt[BH * NH * T_];
__device__ int   g_st [BH * NH * T_];
__device__ float g_oh [BH * NH * T_ * DH];
__device__ float g_lse[BH * NH * T_];
__device__ float g_of [BH * T_ * DH];

// ---------------- stage 1: maxpool + Haar -> tokens ------------------------
__global__ __launch_bounds__(256) void k_tokens(const float* __restrict__ x) {
    int idx = blockIdx.x * 256 + threadIdx.x;
    if (idx >= B_ * NTOK * S_) return;
    int s = idx & 255;
    int n = (idx >> 8) % NTOK;
    int b = idx / (NTOK * S_);
    int hh = s >> 4, ww = s & 15;
    float val;
    if (n < 128) {
        const float* xp = x + (size_t)(b * C_ + n) * HIM * WIM;
        float m = -INFINITY;
        int i0 = 2 * hh - 1, j0 = 2 * ww - 1;
        #pragma unroll
        for (int di = 0; di < 3; di++) {
            int i = i0 + di; if (i < 0 || i >= HIM) continue;
            #pragma unroll
            for (int dj = 0; dj < 3; dj++) {
                int j = j0 + dj; if (j < 0 || j >= WIM) continue;
                m = fmaxf(m, xp[i * WIM + j]);
            }
        }
        val = m;
    } else {
        int g = (n - 128) >> 7;
        int c = (n - 128) & 127;
        const float* xp = x + (size_t)(b * C_ + c) * HIM * WIM;
        float a  = xp[(2 * hh) * WIM + 2 * ww];
        float bb = xp[(2 * hh) * WIM + 2 * ww + 1];
        float cc = xp[(2 * hh + 1) * WIM + 2 * ww];
        float dd = xp[(2 * hh + 1) * WIM + 2 * ww + 1];
        if      (g == 0) val = (a + bb + cc + dd) * 0.5f;
        else if (g == 1) val = (a - bb + cc - dd) * 0.5f;
        else if (g == 2) val = (a + bb - cc - dd) * 0.5f;
        else             val = (a - bb - cc + dd) * 0.5f;
    }
    g_tokens[idx] = val;
}

// ---------------- stage 2: qk/v GEMM -----------------------------------
// M=10240, K=256, N=512. Tile 64x128x16, 256 threads, 4x8 microtile, f32x2.
__global__ __launch_bounds__(256) void k_gemm_qkv(const float* __restrict__ wqk,
                                                  const float* __restrict__ wv) {
    __shared__ float As[64][16];
    __shared__ float Bs[16][128];
    int bm = blockIdx.y * 64;
    int bn = blockIdx.x * 128;         // 0,128,256,384
    const float* Bmat = (bn < 256) ? wqk : wv;
    int bncol = (bn < 256) ? bn : bn - 256;
    int tid = threadIdx.x;
    int tx = tid & 15, ty = tid >> 4;
    u64 acc2[4][4] = {};

    for (int k0 = 0; k0 < S_; k0 += 16) {
        {   // A tile: 64x16
            int i = tid * 4;
            int r = i >> 4, c = i & 15;
            *(float4*)&As[r][c] = *(const float4*)&g_tokens[(size_t)(bm + r) * S_ + k0 + c];
        }
        {   // B tile: 16x128, 2 float4 per thread
            int r = tid >> 4, c = (tid & 15) * 8;
            const float* bp = &Bmat[(size_t)(k0 + r) * EMBD + bncol + c];
            *(float4*)&Bs[r][c]     = *(const float4*)bp;
            *(float4*)&Bs[r][c + 4] = *(const float4*)(bp + 4);
        }
        __syncthreads();
        #pragma unroll
        for (int kk = 0; kk < 16; kk++) {
            ulonglong2 ba = *(const ulonglong2*)&Bs[kk][tx * 8];
            ulonglong2 bb = *(const ulonglong2*)&Bs[kk][tx * 8 + 4];
            #pragma unroll
            for (int r = 0; r < 4; r++) {
                u64 a2 = pk2(As[ty * 4 + r][kk]);
                acc2[r][0] = ffma2(a2, ba.x, acc2[r][0]);
                acc2[r][1] = ffma2(a2, ba.y, acc2[r][1]);
                acc2[r][2] = ffma2(a2, bb.x, acc2[r][2]);
                acc2[r][3] = ffma2(a2, bb.y, acc2[r][3]);
            }
        }
        __syncthreads();
    }
    #pragma unroll
    for (int r = 0; r < 4; r++) {
        int m = bm + ty * 4 + r;
        int b = m / T_, n = m % T_;
        #pragma unroll
        for (int c2 = 0; c2 < 4; c2++) {
            float2 p = upk2(acc2[r][c2]);
            #pragma unroll
            for (int u = 0; u < 2; u++) {
                int e = bn + tx * 8 + c2 * 2 + u;
                float vv = (u == 0) ? p.x : p.y;
                if (e < 256) {
                    int head = e >> 5, dh = e & 31;
                    g_qk[((size_t)(b * NHEAD + head) * T_ + n) * DH + dh] = vv;
                } else {
                    int e2 = e - 256;
                    int head = e2 >> 5, dh = e2 & 31;
                    g_v[((size_t)(b * NHEAD + head) * T_ + n) * DH + dh] = vv;
                }
            }
        }
    }
}

// ---------------- stage 3: LSH buckets ------------------------------------
__global__ __launch_bounds__(256) void k_buckets(const float* __restrict__ rot) {
    __shared__ float srot[DH * NH * 5];
    for (int i = threadIdx.x; i < DH * NH * 5; i += 256) srot[i] = rot[i];
    __syncthreads();
    int gid = blockIdx.x * 256 + threadIdx.x;
    if (gid >= BH * T_) return;
    int bh = gid / T_, t = gid % T_;
    float q[DH];
    const float* qp = &g_qk[((size_t)bh * T_ + t) * DH];
    #pragma unroll
    for (int f = 0; f < DH; f++) q[f] = qp[f];
    #pragma unroll
    for (int h = 0; h < NH; h++) {
        float s[5] = {0, 0, 0, 0, 0};
        for (int f = 0; f < DH; f++) {
            float qf = q[f];
            #pragma unroll
            for (int i = 0; i < 5; i++) s[i] += qf * srot[f * (NH * 5) + h * 5 + i];
        }
        float best = s[0]; int bi = 0;
        #pragma unroll
        for (int i = 1; i < 5; i++) if (s[i] > best) { best = s[i]; bi = i; }
        #pragma unroll
        for (int i = 0; i < 5; i++) if (-s[i] > best) { best = -s[i]; bi = 5 + i; }
        g_bkt[(size_t)(bh * NH + h) * T_ + t] = bi;
    }
}

// ---------------- stage 4: stable counting sort ----------------------------
__global__ __launch_bounds__(T_) void k_sort() {
    int bhh = blockIdx.x;
    __shared__ unsigned smask[T_ / 32][NB];
    __shared__ int off[NB];
    int t = threadIdx.x;
    int w = t >> 5, lane = t & 31;
    int b = g_bkt[(size_t)bhh * T_ + t];
    #pragma unroll
    for (int bb = 0; bb < NB; bb++) {
        unsigned m = __ballot_sync(0xffffffff, b == bb);
        if (lane == 0) smask[w][bb] = m;
    }
    __syncthreads();
    if (t == 0) {
        int acc = 0;
        #pragma unroll
        for (int i = 0; i < NB; i++) {
            off[i] = acc;
            int c = 0;
            #pragma unroll
            for (int ww = 0; ww < T_ / 32; ww++) c += __popc(smask[ww][i]);
            acc += c;
        }
    }
    __syncthreads();
    int rank = 0;
    for (int ww = 0; ww < w; ww++) rank += __popc(smask[ww][b]);
    rank += __popc(smask[w][b] & ((1u << lane) - 1u));
    g_st[(size_t)bhh * T_ + off[b] + rank] = t;
}

// ---------------- stage 5: chunked attention (f32x2) -----------------------
#define ATTN_SMEM 62208
__global__ __launch_bounds__(256) void k_attn() {
    extern __shared__ float smem[];
    float* sS   = smem;                    // [64][132]
    float* sKV  = smem + 8448;             // K^T [32][136] then V [128][36]
    float* sQ   = smem + 13056;            // [64][36]
    int*   sTid = (int*)(smem + 15360);
    float* sLse = smem + 15488;

    int bh = blockIdx.y;
    int n  = blockIdx.x;
    int h  = n / NB;
    int np = (n + NC - 1) % NC;
    int hp = np / NB;
    int tid = threadIdx.x;
    const int* stb = &g_st[(size_t)bh * NH * T_];

    if (tid < 128) {
        int kt = (tid < 64) ? stb[h * T_ + (n % NB) * 64 + tid]
                            : stb[hp * T_ + (np % NB) * 64 + (tid - 64)];
        sTid[tid] = kt;
    }
    __syncthreads();

    {   // Q: 64x32
        int i = tid >> 2, d0 = (tid & 3) * 8;
        const float* qp = &g_qk[((size_t)bh * T_ + sTid[i]) * DH + d0];
        *(float4*)&sQ[i * 36 + d0]     = *(const float4*)qp;
        *(float4*)&sQ[i * 36 + d0 + 4] = *(const float4*)(qp + 4);
    }
    {   // K transpose + normalize
        int j = tid >> 1, d0 = (tid & 1) * 16;
        const float* kp = &g_qk[((size_t)bh * T_ + sTid[j]) * DH + d0];
        float kv[16];
        #pragma unroll
        for (int u = 0; u < 16; u += 4) {
            float4 t4 = *(const float4*)&kp[u];
            kv[u] = t4.x; kv[u + 1] = t4.y; kv[u + 2] = t4.z; kv[u + 3] = t4.w;
        }
        float ss = 0;
        #pragma unroll
        for (int u = 0; u < 16; u++) ss += kv[u] * kv[u];
        ss += __shfl_xor_sync(0xffffffff, ss, 1);
        float inv = 1.0f / fmaxf(sqrtf(ss), 1e-6f);
        #pragma unroll
        for (int u = 0; u < 16; u++) sKV[(d0 + u) * 136 + j] = kv[u] * inv;
    }
    __syncthreads();

    {   // scores: 4 rows x 8 cols (4 f32x2) per thread
        int ty = tid >> 4, tx = tid & 15;
        u64 acc2[4][4] = {};
        #pragma unroll 8
        for (int d = 0; d < DH; d++) {
            ulonglong2 ka = *(const ulonglong2*)&sKV[d * 136 + tx * 8];
            ulonglong2 kb = *(const ulonglong2*)&sKV[d * 136 + tx * 8 + 4];
            #pragma unroll
            for (int r = 0; r < 4; r++) {
                u64 q2 = pk2(sQ[(ty * 4 + r) * 36 + d]);
                acc2[r][0] = ffma2(q2, ka.x, acc2[r][0]);
                acc2[r][1] = ffma2(q2, ka.y, acc2[r][1]);
                acc2[r][2] = ffma2(q2, kb.x, acc2[r][2]);
                acc2[r][3] = ffma2(q2, kb.y, acc2[r][3]);
            }
        }
        const float scale = 0.17677669529663687f;   // 32^-0.5
        #pragma unroll
        for (int r = 0; r < 4; r++) {
            int row = ty * 4 + r;
            int qt = sTid[row];
            float o[8];
            float2 p0 = upk2(acc2[r][0]), p1 = upk2(acc2[r][1]);
            float2 p2 = upk2(acc2[r][2]), p3 = upk2(acc2[r][3]);
            o[0] = p0.x; o[1] = p0.y; o[2] = p1.x; o[3] = p1.y;
            o[4] = p2.x; o[5] = p2.y; o[6] = p3.x; o[7] = p3.y;
            #pragma unroll
            for (int c = 0; c < 8; c++) {
                int kt = sTid[tx * 8 + c];
                o[c] = (qt == kt) ? -50000.0f : o[c] * scale;
            }
            *(float4*)&sS[row * 132 + tx * 8]     = make_float4(o[0], o[1], o[2], o[3]);
            *(float4*)&sS[row * 132 + tx * 8 + 4] = make_float4(o[4], o[5], o[6], o[7]);
        }
    }
    __syncthreads();

    {   // V into sKV (row-major)
        int j = tid >> 1, d0 = (tid & 1) * 16;
        const float* vp = &g_v[((size_t)bh * T_ + sTid[j]) * DH + d0];
        #pragma unroll
        for (int u = 0; u < 16; u += 4)
            *(float4*)&sKV[j * 36 + d0 + u] = *(const float4*)&vp[u];
    }
    {   // softmax
        int row = tid >> 2, part = tid & 3;
        float v[32];
        #pragma unroll
        for (int u = 0; u < 8; u++) {
            float4 t4 = *(const float4*)&sS[row * 132 + part * 32 + u * 4];
            v[4*u] = t4.x; v[4*u+1] = t4.y; v[4*u+2] = t4.z; v[4*u+3] = t4.w;
        }
        float m = v[0];
        #pragma unroll
        for (int u = 1; u < 32; u++) m = fmaxf(m, v[u]);
        m = fmaxf(m, __shfl_xor_sync(0xffffffff, m, 1));
        m = fmaxf(m, __shfl_xor_sync(0xffffffff, m, 2));
        float sum = 0;
        #pragma unroll
        for (int u = 0; u < 32; u++) { v[u] = __expf(v[u] - m); sum += v[u]; }
        sum += __shfl_xor_sync(0xffffffff, sum, 1);
        sum += __shfl_xor_sync(0xffffffff, sum, 2);
        float inv = 1.0f / sum;
        #pragma unroll
        for (int u = 0; u < 8; u++)
            *(float4*)&sS[row * 132 + part * 32 + u * 4] =
                make_float4(v[4*u] * inv, v[4*u+1] * inv, v[4*u+2] * inv, v[4*u+3] * inv);
        if (part == 0) sLse[row] = m + __logf(sum);
    }
    __syncthreads();

    {   // PV: 2 rows x 4 dims (2 f32x2) per thread
        int qi = tid >> 3;
        int dc = (tid & 7) * 4;
        u64 a0[2] = {}, a1[2] = {};
        #pragma unroll 4
        for (int j = 0; j < 128; j += 4) {
            float4 p0 = *(const float4*)&sS[(2 * qi) * 132 + j];
            float4 p1 = *(const float4*)&sS[(2 * qi + 1) * 132 + j];
            float p0a[4] = {p0.x, p0.y, p0.z, p0.w};
            float p1a[4] = {p1.x, p1.y, p1.z, p1.w};
            #pragma unroll
            for (int u = 0; u < 4; u++) {
                ulonglong2 vv = *(const ulonglong2*)&sKV[(j + u) * 36 + dc];
                u64 q0 = pk2(p0a[u]), q1 = pk2(p1a[u]);
                a0[0] = ffma2(q0, vv.x, a0[0]); a0[1] = ffma2(q0, vv.y, a0[1]);
                a1[0] = ffma2(q1, vv.x, a1[0]); a1[1] = ffma2(q1, vv.y, a1[1]);
            }
        }
        float2 f00 = upk2(a0[0]), f01 = upk2(a0[1]);
        float2 f10 = upk2(a1[0]), f11 = upk2(a1[1]);
        int qt0 = sTid[2 * qi], qt1 = sTid[2 * qi + 1];
        size_t hb = (size_t)(bh * NH + h) * T_;
        *(float4*)&g_oh[(hb + qt0) * DH + dc] = make_float4(f00.x, f00.y, f01.x, f01.y);
        *(float4*)&g_oh[(hb + qt1) * DH + dc] = make_float4(f10.x, f10.y, f11.x, f11.y);
        if ((tid & 7) == 0) {
            g_lse[hb + qt0] = sLse[2 * qi];
            g_lse[hb + qt1] = sLse[2 * qi + 1];
        }
    }
}

// ---------------- stage 6: combine over hashes -----------------------------
__global__ __launch_bounds__(256) void k_combine() {
    int w = blockIdx.x * 8 + (threadIdx.x >> 5);
    int lane = threadIdx.x & 31;
    int bh = w / T_, t = w % T_;
    float l[NH];
    #pragma unroll
    for (int h = 0; h < NH; h++) l[h] = g_lse[(size_t)(bh * NH + h) * T_ + t];
    float m = l[0];
    #pragma unroll
    for (int h = 1; h < NH; h++) m = fmaxf(m, l[h]);
    float sum = 0;
    #pragma unroll
    for (int h = 0; h < NH; h++) { l[h] = __expf(l[h] - m); sum += l[h]; }
    float inv = 1.0f / sum;
    float o = 0;
    #pragma unroll
    for (int h = 0; h < NH; h++)
        o += l[h] * inv * g_oh[((size_t)(bh * NH + h) * T_ + t) * DH + lane];
    g_of[((size_t)bh * T_ + t) * DH + lane] = o;
}

// ---------------- stage 7: output GEMM + bias ------------------------------
// M=10240, K=256, N=256. Tile 64x128x16, 4x8 microtile, f32x2.
__global__ __launch_bounds__(256) void k_gemm_out(const float* __restrict__ wout,
                                                  const float* __restrict__ bias,
                                                  float* __restrict__ out) {
    __shared__ float As[64][16];
    __shared__ float Bs[16][128];
    int bm = blockIdx.y * 64;
    int bn = blockIdx.x * 128;
    int tid = threadIdx.x;
    int tx = tid & 15, ty = tid >> 4;
    u64 acc2[4][4] = {};

    for (int k0 = 0; k0 < EMBD; k0 += 16) {
        {   // gather A from head-major g_of
            int i = tid * 4;
            int r = i >> 4, c = i & 15;
            int m = bm + r;
            int b = m / T_, n = m % T_;
            int k = k0 + c;
            int head = k >> 5, dh = k & 31;
            *(float4*)&As[r][c] =
                *(const float4*)&g_of[((size_t)(b * NHEAD + head) * T_ + n) * DH + dh];
        }
        {
            int r = tid >> 4, c = (tid & 15) * 8;
            const float* bp = &wout[(size_t)(k0 + r) * EMBD + bn + c];
            *(float4*)&Bs[r][c]     = *(const float4*)bp;
            *(float4*)&Bs[r][c + 4] = *(const float4*)(bp + 4);
        }
        __syncthreads();
        #pragma unroll
        for (int kk = 0; kk < 16; kk++) {
            ulonglong2 ba = *(const ulonglong2*)&Bs[kk][tx * 8];
            ulonglong2 bb = *(const ulonglong2*)&Bs[kk][tx * 8 + 4];
            #pragma unroll
            for (int r = 0; r < 4; r++) {
                u64 a2 = pk2(As[ty * 4 + r][kk]);
                acc2[r][0] = ffma2(a2, ba.x, acc2[r][0]);
                acc2[r][1] = ffma2(a2, ba.y, acc2[r][1]);
                acc2[r][2] = ffma2(a2, bb.x, acc2[r][2]);
                acc2[r][3] = ffma2(a2, bb.y, acc2[r][3]);
            }
        }
        __syncthreads();
    }
    #pragma unroll
    for (int r = 0; r < 4; r++) {
        int m = bm + ty * 4 + r;
        #pragma unroll
        for (int c2 = 0; c2 < 4; c2++) {
            float2 p = upk2(acc2[r][c2]);
            int e = bn + tx * 8 + c2 * 2;
            out[(size_t)m * EMBD + e]     = p.x + bias[e];
            out[(size_t)m * EMBD + e + 1] = p.y + bias[e + 1];
        }
    }
}

// ---------------- launch ----------------------------------------------------
extern "C" void kernel_launch(void* const* d_in, const int* in_sizes, int n_in,
                              void* d_out, int out_size) {
    const float* x    = (const float*)d_in[0];
    const float* wqk  = (const float*)d_in[1];
    const float* wv   = (const float*)d_in[2];
    const float* wout = (const float*)d_in[3];
    const float* bout = (const float*)d_in[4];
    const float* rot  = (const float*)d_in[5];
    float* out = (float*)d_out;

    cudaFuncSetAttribute(k_attn, cudaFuncAttributeMaxDynamicSharedMemorySize, ATTN_SMEM);

    k_tokens  <<<(B_ * NTOK * S_ + 255) / 256, 256>>>(x);
    k_gemm_qkv<<<dim3(4, 160), 256>>>(wqk, wv);
    k_buckets <<<(BH * T_ + 255) / 256, 256>>>(rot);
    k_sort    <<<BH * NH, T_>>>();
    k_attn    <<<dim3(80, 128), 256, ATTN_SMEM>>>();
    k_combine <<<BH * T_ / 8, 256>>>();
    k_gemm_out<<<dim3(2, 160), 256>>>(wout, bout, out);
}

// round 12
// speedup vs baseline: 1.0745x; 1.0745x over previous
#include <cuda_runtime.h>
#include <math.h>

#define B_    16
#define C_    128
#define HIM   32
#define WIM   32
#define NTOK  640
#define S_    256
#define EMBD  256
#define NHEAD 8
#define DH    32
#define BH    128
#define T_    640
#define NH    8
#define NB    10
#define NC    80

// ---------------- scratch ----------------
__device__ float g_tokens[B_ * NTOK * S_];
__device__ float g_qk[BH * T_ * DH];
__device__ float g_v [BH * T_ * DH];
__device__ int   g_bkt[BH * NH * T_];
__device__ int   g_st [BH * NH * T_];
__device__ float g_oh [BH * NH * T_ * DH];
__device__ float g_lse[BH * NH * T_];
__device__ float g_of [BH * T_ * DH];

// ---------------- stage 1: maxpool + Haar -> tokens ------------------------
__global__ __launch_bounds__(256) void k_tokens(const float* __restrict__ x) {
    int idx = blockIdx.x * 256 + threadIdx.x;
    if (idx >= B_ * NTOK * S_) return;
    int s = idx & 255;
    int n = (idx >> 8) % NTOK;
    int b = idx / (NTOK * S_);
    int hh = s >> 4, ww = s & 15;
    float val;
    if (n < 128) {
        const float* xp = x + (size_t)(b * C_ + n) * HIM * WIM;
        float m = -INFINITY;
        int i0 = 2 * hh - 1, j0 = 2 * ww - 1;
        #pragma unroll
        for (int di = 0; di < 3; di++) {
            int i = i0 + di; if (i < 0 || i >= HIM) continue;
            #pragma unroll
            for (int dj = 0; dj < 3; dj++) {
                int j = j0 + dj; if (j < 0 || j >= WIM) continue;
                m = fmaxf(m, xp[i * WIM + j]);
            }
        }
        val = m;
    } else {
        int g = (n - 128) >> 7;
        int c = (n - 128) & 127;
        const float* xp = x + (size_t)(b * C_ + c) * HIM * WIM;
        float a  = xp[(2 * hh) * WIM + 2 * ww];
        float bb = xp[(2 * hh) * WIM + 2 * ww + 1];
        float cc = xp[(2 * hh + 1) * WIM + 2 * ww];
        float dd = xp[(2 * hh + 1) * WIM + 2 * ww + 1];
        if      (g == 0) val = (a + bb + cc + dd) * 0.5f;
        else if (g == 1) val = (a - bb + cc - dd) * 0.5f;
        else if (g == 2) val = (a + bb - cc - dd) * 0.5f;
        else             val = (a - bb - cc + dd) * 0.5f;
    }
    g_tokens[idx] = val;
}

// ---------------- stage 2: qk/v GEMM -----------------------------------
// M=10240, K=256, N=512. Tile 128x128x16, 256 threads, 8x8 microtile.
// A stored transposed in smem so both operand loads are LDS.128 + broadcast.
__global__ __launch_bounds__(256) void k_gemm_qkv(const float* __restrict__ wqk,
                                                  const float* __restrict__ wv) {
    __shared__ float AsT[16][132];     // [k][m]
    __shared__ float Bs[16][128];      // [k][n]
    int bm = blockIdx.y * 128;
    int bn = blockIdx.x * 128;         // 0,128,256,384
    const float* Bmat = (bn < 256) ? wqk : wv;
    int bncol = bn & 255;
    int tid = threadIdx.x;
    int tx = tid & 15, ty = tid >> 4;
    float acc[8][8] = {};

    for (int k0 = 0; k0 < S_; k0 += 16) {
        #pragma unroll
        for (int it = 0; it < 2; it++) {   // A: 128x16, transposed store
            int idx = tid * 2 + it;
            int r = idx >> 2, cq = (idx & 3) * 4;
            float4 av = *(const float4*)&g_tokens[(size_t)(bm + r) * S_ + k0 + cq];
            AsT[cq][r] = av.x; AsT[cq + 1][r] = av.y;
            AsT[cq + 2][r] = av.z; AsT[cq + 3][r] = av.w;
        }
        #pragma unroll
        for (int it = 0; it < 2; it++) {   // B: 16x128
            int idx = tid * 2 + it;
            int r = idx >> 5, c = (idx & 31) * 4;
            *(float4*)&Bs[r][c] = *(const float4*)&Bmat[(size_t)(k0 + r) * EMBD + bncol + c];
        }
        __syncthreads();
        #pragma unroll
        for (int kk = 0; kk < 16; kk++) {
            float a[8], b[8];
            *(float4*)&a[0] = *(const float4*)&AsT[kk][ty * 8];
            *(float4*)&a[4] = *(const float4*)&AsT[kk][ty * 8 + 4];
            *(float4*)&b[0] = *(const float4*)&Bs[kk][tx * 8];
            *(float4*)&b[4] = *(const float4*)&Bs[kk][tx * 8 + 4];
            #pragma unroll
            for (int r = 0; r < 8; r++)
                #pragma unroll
                for (int c = 0; c < 8; c++)
                    acc[r][c] += a[r] * b[c];
        }
        __syncthreads();
    }
    // epilogue: 8 consecutive e stay within one head (tx*8 is 8-aligned)
    int e0 = bn + tx * 8;
    float* dst = (e0 < 256) ? g_qk : g_v;
    int ec = e0 & 255;
    int head = ec >> 5, dh = ec & 31;
    #pragma unroll
    for (int r = 0; r < 8; r++) {
        int m = bm + ty * 8 + r;
        int b = m / T_, n = m % T_;
        size_t base = ((size_t)(b * NHEAD + head) * T_ + n) * DH + dh;
        *(float4*)&dst[base]     = make_float4(acc[r][0], acc[r][1], acc[r][2], acc[r][3]);
        *(float4*)&dst[base + 4] = make_float4(acc[r][4], acc[r][5], acc[r][6], acc[r][7]);
    }
}

// ---------------- stage 3: LSH buckets ------------------------------------
__global__ __launch_bounds__(256) void k_buckets(const float* __restrict__ rot) {
    __shared__ float srot[DH * NH * 5];
    for (int i = threadIdx.x; i < DH * NH * 5; i += 256) srot[i] = rot[i];
    __syncthreads();
    int gid = blockIdx.x * 256 + threadIdx.x;
    if (gid >= BH * T_) return;
    int bh = gid / T_, t = gid % T_;
    float q[DH];
    const float* qp = &g_qk[((size_t)bh * T_ + t) * DH];
    #pragma unroll
    for (int f = 0; f < DH; f++) q[f] = qp[f];
    #pragma unroll
    for (int h = 0; h < NH; h++) {
        float s[5] = {0, 0, 0, 0, 0};
        for (int f = 0; f < DH; f++) {
            float qf = q[f];
            #pragma unroll
            for (int i = 0; i < 5; i++) s[i] += qf * srot[f * (NH * 5) + h * 5 + i];
        }
        float best = s[0]; int bi = 0;
        #pragma unroll
        for (int i = 1; i < 5; i++) if (s[i] > best) { best = s[i]; bi = i; }
        #pragma unroll
        for (int i = 0; i < 5; i++) if (-s[i] > best) { best = -s[i]; bi = 5 + i; }
        g_bkt[(size_t)(bh * NH + h) * T_ + t] = bi;
    }
}

// ---------------- stage 4: stable counting sort ----------------------------
__global__ __launch_bounds__(T_) void k_sort() {
    int bhh = blockIdx.x;
    __shared__ unsigned smask[T_ / 32][NB];
    __shared__ int off[NB];
    int t = threadIdx.x;
    int w = t >> 5, lane = t & 31;
    int b = g_bkt[(size_t)bhh * T_ + t];
    #pragma unroll
    for (int bb = 0; bb < NB; bb++) {
        unsigned m = __ballot_sync(0xffffffff, b == bb);
        if (lane == 0) smask[w][bb] = m;
    }
    __syncthreads();
    if (t == 0) {
        int acc = 0;
        #pragma unroll
        for (int i = 0; i < NB; i++) {
            off[i] = acc;
            int c = 0;
            #pragma unroll
            for (int ww = 0; ww < T_ / 32; ww++) c += __popc(smask[ww][i]);
            acc += c;
        }
    }
    __syncthreads();
    int rank = 0;
    for (int ww = 0; ww < w; ww++) rank += __popc(smask[ww][b]);
    rank += __popc(smask[w][b] & ((1u << lane) - 1u));
    g_st[(size_t)bhh * T_ + off[b] + rank] = t;
}

// ---------------- stage 5: chunked attention (R5 known-good) ---------------
#define ATTN_SMEM 62208
__global__ __launch_bounds__(256) void k_attn() {
    extern __shared__ float smem[];
    float* sS   = smem;                    // [64][132]
    float* sKV  = smem + 8448;             // K^T [32][136] then V [128][36]
    float* sQ   = smem + 13056;            // [64][36]
    int*   sTid = (int*)(smem + 15360);
    float* sLse = smem + 15488;

    int bh = blockIdx.y;
    int n  = blockIdx.x;
    int h  = n / NB;
    int np = (n + NC - 1) % NC;
    int hp = np / NB;
    int tid = threadIdx.x;
    const int* stb = &g_st[(size_t)bh * NH * T_];

    if (tid < 128) {
        int kt = (tid < 64) ? stb[h * T_ + (n % NB) * 64 + tid]
                            : stb[hp * T_ + (np % NB) * 64 + (tid - 64)];
        sTid[tid] = kt;
    }
    __syncthreads();

    {   // Q: 64x32
        int i = tid >> 2, d0 = (tid & 3) * 8;
        const float* qp = &g_qk[((size_t)bh * T_ + sTid[i]) * DH + d0];
        *(float4*)&sQ[i * 36 + d0]     = *(const float4*)qp;
        *(float4*)&sQ[i * 36 + d0 + 4] = *(const float4*)(qp + 4);
    }
    {   // K transpose + normalize
        int j = tid >> 1, d0 = (tid & 1) * 16;
        const float* kp = &g_qk[((size_t)bh * T_ + sTid[j]) * DH + d0];
        float kv[16];
        #pragma unroll
        for (int u = 0; u < 16; u += 4) {
            float4 t4 = *(const float4*)&kp[u];
            kv[u] = t4.x; kv[u + 1] = t4.y; kv[u + 2] = t4.z; kv[u + 3] = t4.w;
        }
        float ss = 0;
        #pragma unroll
        for (int u = 0; u < 16; u++) ss += kv[u] * kv[u];
        ss += __shfl_xor_sync(0xffffffff, ss, 1);
        float inv = 1.0f / fmaxf(sqrtf(ss), 1e-6f);
        #pragma unroll
        for (int u = 0; u < 16; u++) sKV[(d0 + u) * 136 + j] = kv[u] * inv;
    }
    __syncthreads();

    {   // scores: 4 rows x 8 cols per thread; K loads are LDS.128 on K^T
        int ty = tid >> 4, tx = tid & 15;
        float acc[4][8] = {};
        #pragma unroll 4
        for (int d = 0; d < DH; d++) {
            float4 k0 = *(const float4*)&sKV[d * 136 + tx * 8];
            float4 k1 = *(const float4*)&sKV[d * 136 + tx * 8 + 4];
            float kk[8] = {k0.x, k0.y, k0.z, k0.w, k1.x, k1.y, k1.z, k1.w};
            #pragma unroll
            for (int r = 0; r < 4; r++) {
                float q = sQ[(ty * 4 + r) * 36 + d];
                #pragma unroll
                for (int c = 0; c < 8; c++) acc[r][c] += q * kk[c];
            }
        }
        const float scale = 0.17677669529663687f;   // 32^-0.5
        #pragma unroll
        for (int r = 0; r < 4; r++) {
            int row = ty * 4 + r;
            int qt = sTid[row];
            float o[8];
            #pragma unroll
            for (int c = 0; c < 8; c++) {
                int kt = sTid[tx * 8 + c];
                o[c] = (qt == kt) ? -50000.0f : acc[r][c] * scale;
            }
            *(float4*)&sS[row * 132 + tx * 8]     = make_float4(o[0], o[1], o[2], o[3]);
            *(float4*)&sS[row * 132 + tx * 8 + 4] = make_float4(o[4], o[5], o[6], o[7]);
        }
    }
    __syncthreads();

    {   // V into sKV (row-major, K^T dead)
        int j = tid >> 1, d0 = (tid & 1) * 16;
        const float* vp = &g_v[((size_t)bh * T_ + sTid[j]) * DH + d0];
        #pragma unroll
        for (int u = 0; u < 16; u += 4)
            *(float4*)&sKV[j * 36 + d0 + u] = *(const float4*)&vp[u];
    }
    {   // softmax: 4 threads per row, 32 entries each
        int row = tid >> 2, part = tid & 3;
        float v[32];
        #pragma unroll
        for (int u = 0; u < 8; u++) {
            float4 t4 = *(const float4*)&sS[row * 132 + part * 32 + u * 4];
            v[4*u] = t4.x; v[4*u+1] = t4.y; v[4*u+2] = t4.z; v[4*u+3] = t4.w;
        }
        float m = v[0];
        #pragma unroll
        for (int u = 1; u < 32; u++) m = fmaxf(m, v[u]);
        m = fmaxf(m, __shfl_xor_sync(0xffffffff, m, 1));
        m = fmaxf(m, __shfl_xor_sync(0xffffffff, m, 2));
        float sum = 0;
        #pragma unroll
        for (int u = 0; u < 32; u++) { v[u] = __expf(v[u] - m); sum += v[u]; }
        sum += __shfl_xor_sync(0xffffffff, sum, 1);
        sum += __shfl_xor_sync(0xffffffff, sum, 2);
        float inv = 1.0f / sum;
        #pragma unroll
        for (int u = 0; u < 8; u++)
            *(float4*)&sS[row * 132 + part * 32 + u * 4] =
                make_float4(v[4*u] * inv, v[4*u+1] * inv, v[4*u+2] * inv, v[4*u+3] * inv);
        if (part == 0) sLse[row] = m + __logf(sum);
    }
    __syncthreads();

    {   // PV: 2 rows x 4 dims per thread, j blocked by 4 (all float4)
        int qi = tid >> 3;
        int dc = (tid & 7) * 4;
        float4 a0 = make_float4(0, 0, 0, 0), a1 = make_float4(0, 0, 0, 0);
        #pragma unroll 4
        for (int j = 0; j < 128; j += 4) {
            float4 p0 = *(const float4*)&sS[(2 * qi) * 132 + j];
            float4 p1 = *(const float4*)&sS[(2 * qi + 1) * 132 + j];
            float p0a[4] = {p0.x, p0.y, p0.z, p0.w};
            float p1a[4] = {p1.x, p1.y, p1.z, p1.w};
            #pragma unroll
            for (int u = 0; u < 4; u++) {
                float4 vv = *(const float4*)&sKV[(j + u) * 36 + dc];
                a0.x += p0a[u] * vv.x; a0.y += p0a[u] * vv.y;
                a0.z += p0a[u] * vv.z; a0.w += p0a[u] * vv.w;
                a1.x += p1a[u] * vv.x; a1.y += p1a[u] * vv.y;
                a1.z += p1a[u] * vv.z; a1.w += p1a[u] * vv.w;
            }
        }
        int qt0 = sTid[2 * qi], qt1 = sTid[2 * qi + 1];
        size_t hb = (size_t)(bh * NH + h) * T_;
        *(float4*)&g_oh[(hb + qt0) * DH + dc] = a0;
        *(float4*)&g_oh[(hb + qt1) * DH + dc] = a1;
        if ((tid & 7) == 0) {
            g_lse[hb + qt0] = sLse[2 * qi];
            g_lse[hb + qt1] = sLse[2 * qi + 1];
        }
    }
}

// ---------------- stage 6: combine over hashes -----------------------------
__global__ __launch_bounds__(256) void k_combine() {
    int w = blockIdx.x * 8 + (threadIdx.x >> 5);
    int lane = threadIdx.x & 31;
    int bh = w / T_, t = w % T_;
    float l[NH];
    #pragma unroll
    for (int h = 0; h < NH; h++) l[h] = g_lse[(size_t)(bh * NH + h) * T_ + t];
    float m = l[0];
    #pragma unroll
    for (int h = 1; h < NH; h++) m = fmaxf(m, l[h]);
    float sum = 0;
    #pragma unroll
    for (int h = 0; h < NH; h++) { l[h] = __expf(l[h] - m); sum += l[h]; }
    float inv = 1.0f / sum;
    float o = 0;
    #pragma unroll
    for (int h = 0; h < NH; h++)
        o += l[h] * inv * g_oh[((size_t)(bh * NH + h) * T_ + t) * DH + lane];
    g_of[((size_t)bh * T_ + t) * DH + lane] = o;
}

// ---------------- stage 7: output GEMM + bias ------------------------------
// M=10240, K=256, N=256. Tile 128x128x16, 8x8 microtile, transposed A.
__global__ __launch_bounds__(256) void k_gemm_out(const float* __restrict__ wout,
                                                  const float* __restrict__ bias,
                                                  float* __restrict__ out) {
    __shared__ float AsT[16][132];
    __shared__ float Bs[16][128];
    int bm = blockIdx.y * 128;
    int bn = blockIdx.x * 128;
    int tid = threadIdx.x;
    int tx = tid & 15, ty = tid >> 4;
    float acc[8][8] = {};

    for (int k0 = 0; k0 < EMBD; k0 += 16) {
        #pragma unroll
        for (int it = 0; it < 2; it++) {   // gather A from head-major g_of, transpose
            int idx = tid * 2 + it;
            int r = idx >> 2, cq = (idx & 3) * 4;
            int m = bm + r;
            int b = m / T_, n = m % T_;
            int k = k0 + cq;
            int head = k >> 5, dh = k & 31;    // 4-aligned, stays within head
            float4 av = *(const float4*)&g_of[((size_t)(b * NHEAD + head) * T_ + n) * DH + dh];
            AsT[cq][r] = av.x; AsT[cq + 1][r] = av.y;
            AsT[cq + 2][r] = av.z; AsT[cq + 3][r] = av.w;
        }
        #pragma unroll
        for (int it = 0; it < 2; it++) {
            int idx = tid * 2 + it;
            int r = idx >> 5, c = (idx & 31) * 4;
            *(float4*)&Bs[r][c] = *(const float4*)&wout[(size_t)(k0 + r) * EMBD + bn + c];
        }
        __syncthreads();
        #pragma unroll
        for (int kk = 0; kk < 16; kk++) {
            float a[8], b[8];
            *(float4*)&a[0] = *(const float4*)&AsT[kk][ty * 8];
            *(float4*)&a[4] = *(const float4*)&AsT[kk][ty * 8 + 4];
            *(float4*)&b[0] = *(const float4*)&Bs[kk][tx * 8];
            *(float4*)&b[4] = *(const float4*)&Bs[kk][tx * 8 + 4];
            #pragma unroll
            for (int r = 0; r < 8; r++)
                #pragma unroll
                for (int c = 0; c < 8; c++)
                    acc[r][c] += a[r] * b[c];
        }
        __syncthreads();
    }
    int e0 = bn + tx * 8;
    float4 bl = *(const float4*)&bias[e0];
    float4 bh4 = *(const float4*)&bias[e0 + 4];
    #pragma unroll
    for (int r = 0; r < 8; r++) {
        int m = bm + ty * 8 + r;
        *(float4*)&out[(size_t)m * EMBD + e0] =
            make_float4(acc[r][0] + bl.x, acc[r][1] + bl.y, acc[r][2] + bl.z, acc[r][3] + bl.w);
        *(float4*)&out[(size_t)m * EMBD + e0 + 4] =
            make_float4(acc[r][4] + bh4.x, acc[r][5] + bh4.y, acc[r][6] + bh4.z, acc[r][7] + bh4.w);
    }
}

// ---------------- launch ----------------------------------------------------
extern "C" void kernel_launch(void* const* d_in, const int* in_sizes, int n_in,
                              void* d_out, int out_size) {
    const float* x    = (const float*)d_in[0];
    const float* wqk  = (const float*)d_in[1];
    const float* wv   = (const float*)d_in[2];
    const float* wout = (const float*)d_in[3];
    const float* bout = (const float*)d_in[4];
    const float* rot  = (const float*)d_in[5];
    float* out = (float*)d_out;

    cudaFuncSetAttribute(k_attn, cudaFuncAttributeMaxDynamicSharedMemorySize, ATTN_SMEM);

    k_tokens  <<<(B_ * NTOK * S_ + 255) / 256, 256>>>(x);
    k_gemm_qkv<<<dim3(4, 80), 256>>>(wqk, wv);
    k_buckets <<<(BH * T_ + 255) / 256, 256>>>(rot);
    k_sort    <<<BH * NH, T_>>>();
    k_attn    <<<dim3(80, 128), 256, ATTN_SMEM>>>();
    k_combine <<<BH * T_ / 8, 256>>>();
    k_gemm_out<<<dim3(2, 80), 256>>>(wout, bout, out);
}

// round 16
// speedup vs baseline: 1.1700x; 1.0888x over previous
#include <cuda_runtime.h>
#include <math.h>

#define B_    16
#define C_    128
#define HIM   32
#define WIM   32
#define NTOK  640
#define S_    256
#define EMBD  256
#define NHEAD 8
#define DH    32
#define BH    128
#define T_    640
#define NH    8
#define NB    10
#define NC    80

// ---------------- scratch ----------------
__device__ float g_tokens[B_ * NTOK * S_];
__device__ float g_qk[BH * T_ * DH];
__device__ float g_v [BH * T_ * DH];
__device__ int   g_bkt[BH * NH * T_];
__device__ int   g_st [BH * NH * T_];
__device__ float g_oh [BH * NH * T_ * DH];
__device__ float g_lse[BH * NH * T_];
__device__ float g_of [BH * T_ * DH];

// ---------------- stage 1: maxpool + Haar -> tokens ------------------------
__global__ __launch_bounds__(256) void k_tokens(const float* __restrict__ x) {
    int idx = blockIdx.x * 256 + threadIdx.x;
    if (idx >= B_ * NTOK * S_) return;
    int s = idx & 255;
    int n = (idx >> 8) % NTOK;
    int b = idx / (NTOK * S_);
    int hh = s >> 4, ww = s & 15;
    float val;
    if (n < 128) {
        const float* xp = x + (size_t)(b * C_ + n) * HIM * WIM;
        float m = -INFINITY;
        int i0 = 2 * hh - 1, j0 = 2 * ww - 1;
        #pragma unroll
        for (int di = 0; di < 3; di++) {
            int i = i0 + di; if (i < 0 || i >= HIM) continue;
            #pragma unroll
            for (int dj = 0; dj < 3; dj++) {
                int j = j0 + dj; if (j < 0 || j >= WIM) continue;
                m = fmaxf(m, xp[i * WIM + j]);
            }
        }
        val = m;
    } else {
        int g = (n - 128) >> 7;
        int c = (n - 128) & 127;
        const float* xp = x + (size_t)(b * C_ + c) * HIM * WIM;
        float a  = xp[(2 * hh) * WIM + 2 * ww];
        float bb = xp[(2 * hh) * WIM + 2 * ww + 1];
        float cc = xp[(2 * hh + 1) * WIM + 2 * ww];
        float dd = xp[(2 * hh + 1) * WIM + 2 * ww + 1];
        if      (g == 0) val = (a + bb + cc + dd) * 0.5f;
        else if (g == 1) val = (a - bb + cc - dd) * 0.5f;
        else if (g == 2) val = (a + bb - cc - dd) * 0.5f;
        else             val = (a - bb - cc + dd) * 0.5f;
    }
    g_tokens[idx] = val;
}

// ---------------- stage 2: qk/v GEMM (R5 config: 64x64x16, 4x4) ------------
__global__ __launch_bounds__(256) void k_gemm_qkv(const float* __restrict__ wqk,
                                                  const float* __restrict__ wv) {
    __shared__ float As[64][16];
    __shared__ float Bs[16][64];
    int bm = blockIdx.y * 64;
    int bn = blockIdx.x * 64;
    const float* Bmat = (bn < 256) ? wqk : wv;
    int bncol = (bn < 256) ? bn : bn - 256;
    int tid = threadIdx.x;
    int tx = tid & 15, ty = tid >> 4;
    float acc[4][4] = {};

    for (int k0 = 0; k0 < S_; k0 += 16) {
        {
            int i = tid * 4;
            int r = i >> 4, c = i & 15;
            *(float4*)&As[r][c] = *(const float4*)&g_tokens[(size_t)(bm + r) * S_ + k0 + c];
        }
        {
            int i = tid * 4;
            int r = i >> 6, c = i & 63;
            *(float4*)&Bs[r][c] = *(const float4*)&Bmat[(size_t)(k0 + r) * EMBD + bncol + c];
        }
        __syncthreads();
        #pragma unroll
        for (int kk = 0; kk < 16; kk++) {
            float a[4];
            #pragma unroll
            for (int r = 0; r < 4; r++) a[r] = As[ty * 4 + r][kk];
            float4 b4 = *(const float4*)&Bs[kk][tx * 4];
            float bb[4] = {b4.x, b4.y, b4.z, b4.w};
            #pragma unroll
            for (int r = 0; r < 4; r++)
                #pragma unroll
                for (int c = 0; c < 4; c++)
                    acc[r][c] += a[r] * bb[c];
        }
        __syncthreads();
    }
    #pragma unroll
    for (int r = 0; r < 4; r++) {
        int m = bm + ty * 4 + r;
        int b = m / T_, n = m % T_;
        #pragma unroll
        for (int c = 0; c < 4; c++) {
            int e = bn + tx * 4 + c;
            float vv = acc[r][c];
            if (e < 256) {
                int head = e >> 5, dh = e & 31;
                g_qk[((size_t)(b * NHEAD + head) * T_ + n) * DH + dh] = vv;
            } else {
                int e2 = e - 256;
                int head = e2 >> 5, dh = e2 & 31;
                g_v[((size_t)(b * NHEAD + head) * T_ + n) * DH + dh] = vv;
            }
        }
    }
}

// ---------------- stage 3: LSH buckets ------------------------------------
__global__ __launch_bounds__(256) void k_buckets(const float* __restrict__ rot) {
    __shared__ float srot[DH * NH * 5];
    for (int i = threadIdx.x; i < DH * NH * 5; i += 256) srot[i] = rot[i];
    __syncthreads();
    int gid = blockIdx.x * 256 + threadIdx.x;
    if (gid >= BH * T_) return;
    int bh = gid / T_, t = gid % T_;
    float q[DH];
    const float* qp = &g_qk[((size_t)bh * T_ + t) * DH];
    #pragma unroll
    for (int f = 0; f < DH; f++) q[f] = qp[f];
    #pragma unroll
    for (int h = 0; h < NH; h++) {
        float s[5] = {0, 0, 0, 0, 0};
        for (int f = 0; f < DH; f++) {
            float qf = q[f];
            #pragma unroll
            for (int i = 0; i < 5; i++) s[i] += qf * srot[f * (NH * 5) + h * 5 + i];
        }
        float best = s[0]; int bi = 0;
        #pragma unroll
        for (int i = 1; i < 5; i++) if (s[i] > best) { best = s[i]; bi = i; }
        #pragma unroll
        for (int i = 0; i < 5; i++) if (-s[i] > best) { best = -s[i]; bi = 5 + i; }
        g_bkt[(size_t)(bh * NH + h) * T_ + t] = bi;
    }
}

// ---------------- stage 4: stable counting sort ----------------------------
__global__ __launch_bounds__(T_) void k_sort() {
    int bhh = blockIdx.x;
    __shared__ unsigned smask[T_ / 32][NB];
    __shared__ int off[NB];
    int t = threadIdx.x;
    int w = t >> 5, lane = t & 31;
    int b = g_bkt[(size_t)bhh * T_ + t];
    #pragma unroll
    for (int bb = 0; bb < NB; bb++) {
        unsigned m = __ballot_sync(0xffffffff, b == bb);
        if (lane == 0) smask[w][bb] = m;
    }
    __syncthreads();
    if (t == 0) {
        int acc = 0;
        #pragma unroll
        for (int i = 0; i < NB; i++) {
            off[i] = acc;
            int c = 0;
            #pragma unroll
            for (int ww = 0; ww < T_ / 32; ww++) c += __popc(smask[ww][i]);
            acc += c;
        }
    }
    __syncthreads();
    int rank = 0;
    for (int ww = 0; ww < w; ww++) rank += __popc(smask[ww][b]);
    rank += __popc(smask[w][b] & ((1u << lane) - 1u));
    g_st[(size_t)bhh * T_ + off[b] + rank] = t;
}

// ---------------- stage 5: chunked attention, fused softmax ----------------
// Row (ty,r) of the 64x128 score tile lives in the 16 tx-lanes of one warp;
// warp w computes rows 8w..8w+7 and PV for warp w reads exactly those rows,
// so softmax is warp-local: shfl reductions, probs written to smem ONCE.
#define ATTN_SMEM 62208
__global__ __launch_bounds__(256) void k_attn() {
    extern __shared__ float smem[];
    float* sS   = smem;                    // [64][132] probs
    float* sKV  = smem + 8448;             // K^T [32][136] then V [128][36]
    float* sQ   = smem + 13056;            // [64][36]
    int*   sTid = (int*)(smem + 15360);
    float* sLse = smem + 15488;

    int bh = blockIdx.y;
    int n  = blockIdx.x;
    int h  = n / NB;
    int np = (n + NC - 1) % NC;
    int hp = np / NB;
    int tid = threadIdx.x;
    const int* stb = &g_st[(size_t)bh * NH * T_];

    if (tid < 128) {
        int kt = (tid < 64) ? stb[h * T_ + (n % NB) * 64 + tid]
                            : stb[hp * T_ + (np % NB) * 64 + (tid - 64)];
        sTid[tid] = kt;
    }
    __syncthreads();

    {   // Q: 64x32
        int i = tid >> 2, d0 = (tid & 3) * 8;
        const float* qp = &g_qk[((size_t)bh * T_ + sTid[i]) * DH + d0];
        *(float4*)&sQ[i * 36 + d0]     = *(const float4*)qp;
        *(float4*)&sQ[i * 36 + d0 + 4] = *(const float4*)(qp + 4);
    }
    {   // K transpose + normalize
        int j = tid >> 1, d0 = (tid & 1) * 16;
        const float* kp = &g_qk[((size_t)bh * T_ + sTid[j]) * DH + d0];
        float kv[16];
        #pragma unroll
        for (int u = 0; u < 16; u += 4) {
            float4 t4 = *(const float4*)&kp[u];
            kv[u] = t4.x; kv[u + 1] = t4.y; kv[u + 2] = t4.z; kv[u + 3] = t4.w;
        }
        float ss = 0;
        #pragma unroll
        for (int u = 0; u < 16; u++) ss += kv[u] * kv[u];
        ss += __shfl_xor_sync(0xffffffff, ss, 1);
        float inv = 1.0f / fmaxf(sqrtf(ss), 1e-6f);
        #pragma unroll
        for (int u = 0; u < 16; u++) sKV[(d0 + u) * 136 + j] = kv[u] * inv;
    }
    __syncthreads();

    {   // scores + mask + softmax (warp-local), write probs once
        int ty = tid >> 4, tx = tid & 15;
        float acc[4][8] = {};
        #pragma unroll
        for (int d4 = 0; d4 < DH; d4 += 4) {
            float qa[4][4];
            #pragma unroll
            for (int r = 0; r < 4; r++)
                *(float4*)&qa[r][0] = *(const float4*)&sQ[(ty * 4 + r) * 36 + d4];
            #pragma unroll
            for (int dd = 0; dd < 4; dd++) {
                int d = d4 + dd;
                float4 k0 = *(const float4*)&sKV[d * 136 + tx * 8];
                float4 k1 = *(const float4*)&sKV[d * 136 + tx * 8 + 4];
                float kk[8] = {k0.x, k0.y, k0.z, k0.w, k1.x, k1.y, k1.z, k1.w};
                #pragma unroll
                for (int r = 0; r < 4; r++) {
                    float q = qa[r][dd];
                    #pragma unroll
                    for (int c = 0; c < 8; c++) acc[r][c] += q * kk[c];
                }
            }
        }
        const float scale = 0.17677669529663687f;   // 32^-0.5
        int kt[8];
        #pragma unroll
        for (int c = 0; c < 8; c++) kt[c] = sTid[tx * 8 + c];
        #pragma unroll
        for (int r = 0; r < 4; r++) {
            int row = ty * 4 + r;
            int qt = sTid[row];
            float o[8];
            #pragma unroll
            for (int c = 0; c < 8; c++)
                o[c] = (qt == kt[c]) ? -50000.0f : acc[r][c] * scale;
            float m = o[0];
            #pragma unroll
            for (int c = 1; c < 8; c++) m = fmaxf(m, o[c]);
            m = fmaxf(m, __shfl_xor_sync(0xffffffff, m, 1));
            m = fmaxf(m, __shfl_xor_sync(0xffffffff, m, 2));
            m = fmaxf(m, __shfl_xor_sync(0xffffffff, m, 4));
            m = fmaxf(m, __shfl_xor_sync(0xffffffff, m, 8));
            float s = 0;
            #pragma unroll
            for (int c = 0; c < 8; c++) { o[c] = __expf(o[c] - m); s += o[c]; }
            s += __shfl_xor_sync(0xffffffff, s, 1);
            s += __shfl_xor_sync(0xffffffff, s, 2);
            s += __shfl_xor_sync(0xffffffff, s, 4);
            s += __shfl_xor_sync(0xffffffff, s, 8);
            float inv = 1.0f / s;
            *(float4*)&sS[row * 132 + tx * 8] =
                make_float4(o[0] * inv, o[1] * inv, o[2] * inv, o[3] * inv);
            *(float4*)&sS[row * 132 + tx * 8 + 4] =
                make_float4(o[4] * inv, o[5] * inv, o[6] * inv, o[7] * inv);
            if (tx == 0) sLse[row] = m + __logf(s);
        }
    }
    __syncthreads();

    {   // V into sKV (K^T dead)
        int j = tid >> 1, d0 = (tid & 1) * 16;
        const float* vp = &g_v[((size_t)bh * T_ + sTid[j]) * DH + d0];
        #pragma unroll
        for (int u = 0; u < 16; u += 4)
            *(float4*)&sKV[j * 36 + d0 + u] = *(const float4*)&vp[u];
    }
    __syncthreads();

    {   // PV: 2 rows x 4 dims per thread, j blocked by 4 (all float4)
        int qi = tid >> 3;
        int dc = (tid & 7) * 4;
        float4 a0 = make_float4(0, 0, 0, 0), a1 = make_float4(0, 0, 0, 0);
        #pragma unroll 4
        for (int j = 0; j < 128; j += 4) {
            float4 p0 = *(const float4*)&sS[(2 * qi) * 132 + j];
            float4 p1 = *(const float4*)&sS[(2 * qi + 1) * 132 + j];
            float p0a[4] = {p0.x, p0.y, p0.z, p0.w};
            float p1a[4] = {p1.x, p1.y, p1.z, p1.w};
            #pragma unroll
            for (int u = 0; u < 4; u++) {
                float4 vv = *(const float4*)&sKV[(j + u) * 36 + dc];
                a0.x += p0a[u] * vv.x; a0.y += p0a[u] * vv.y;
                a0.z += p0a[u] * vv.z; a0.w += p0a[u] * vv.w;
                a1.x += p1a[u] * vv.x; a1.y += p1a[u] * vv.y;
                a1.z += p1a[u] * vv.z; a1.w += p1a[u] * vv.w;
            }
        }
        int qt0 = sTid[2 * qi], qt1 = sTid[2 * qi + 1];
        size_t hb = (size_t)(bh * NH + h) * T_;
        *(float4*)&g_oh[(hb + qt0) * DH + dc] = a0;
        *(float4*)&g_oh[(hb + qt1) * DH + dc] = a1;
        if ((tid & 7) == 0) {
            g_lse[hb + qt0] = sLse[2 * qi];
            g_lse[hb + qt1] = sLse[2 * qi + 1];
        }
    }
}

// ---------------- stage 6: combine over hashes -----------------------------
__global__ __launch_bounds__(256) void k_combine() {
    int w = blockIdx.x * 8 + (threadIdx.x >> 5);
    int lane = threadIdx.x & 31;
    int bh = w / T_, t = w % T_;
    float l[NH];
    #pragma unroll
    for (int h = 0; h < NH; h++) l[h] = g_lse[(size_t)(bh * NH + h) * T_ + t];
    float m = l[0];
    #pragma unroll
    for (int h = 1; h < NH; h++) m = fmaxf(m, l[h]);
    float sum = 0;
    #pragma unroll
    for (int h = 0; h < NH; h++) { l[h] = __expf(l[h] - m); sum += l[h]; }
    float inv = 1.0f / sum;
    float o = 0;
    #pragma unroll
    for (int h = 0; h < NH; h++)
        o += l[h] * inv * g_oh[((size_t)(bh * NH + h) * T_ + t) * DH + lane];
    g_of[((size_t)bh * T_ + t) * DH + lane] = o;
}

// ---------------- stage 7: output GEMM + bias (R5 config) ------------------
__global__ __launch_bounds__(256) void k_gemm_out(const float* __restrict__ wout,
                                                  const float* __restrict__ bias,
                                                  float* __restrict__ out) {
    __shared__ float As[64][16];
    __shared__ float Bs[16][64];
    int bm = blockIdx.y * 64;
    int bn = blockIdx.x * 64;
    int tid = threadIdx.x;
    int tx = tid & 15, ty = tid >> 4;
    float acc[4][4] = {};

    for (int k0 = 0; k0 < EMBD; k0 += 16) {
        {
            int i = tid * 4;
            int r = i >> 4, c = i & 15;
            int m = bm + r;
            int b = m / T_, n = m % T_;
            int k = k0 + c;
            int head = k >> 5, dh = k & 31;
            *(float4*)&As[r][c] =
                *(const float4*)&g_of[((size_t)(b * NHEAD + head) * T_ + n) * DH + dh];
        }
        {
            int i = tid * 4;
            int r = i >> 6, c = i & 63;
            *(float4*)&Bs[r][c] = *(const float4*)&wout[(size_t)(k0 + r) * EMBD + bn + c];
        }
        __syncthreads();
        #pragma unroll
        for (int kk = 0; kk < 16; kk++) {
            float a[4];
            #pragma unroll
            for (int r = 0; r < 4; r++) a[r] = As[ty * 4 + r][kk];
            float4 b4 = *(const float4*)&Bs[kk][tx * 4];
            float bb[4] = {b4.x, b4.y, b4.z, b4.w};
            #pragma unroll
            for (int r = 0; r < 4; r++)
                #pragma unroll
                for (int c = 0; c < 4; c++)
                    acc[r][c] += a[r] * bb[c];
        }
        __syncthreads();
    }
    #pragma unroll
    for (int r = 0; r < 4; r++) {
        int m = bm + ty * 4 + r;
        #pragma unroll
        for (int c = 0; c < 4; c++) {
            int e = bn + tx * 4 + c;
            out[(size_t)m * EMBD + e] = acc[r][c] + bias[e];
        }
    }
}

// ---------------- launch ----------------------------------------------------
extern "C" void kernel_launch(void* const* d_in, const int* in_sizes, int n_in,
                              void* d_out, int out_size) {
    const float* x    = (const float*)d_in[0];
    const float* wqk  = (const float*)d_in[1];
    const float* wv   = (const float*)d_in[2];
    const float* wout = (const float*)d_in[3];
    const float* bout = (const float*)d_in[4];
    const float* rot  = (const float*)d_in[5];
    float* out = (float*)d_out;

    cudaFuncSetAttribute(k_attn, cudaFuncAttributeMaxDynamicSharedMemorySize, ATTN_SMEM);

    k_tokens  <<<(B_ * NTOK * S_ + 255) / 256, 256>>>(x);
    k_gemm_qkv<<<dim3(8, 160), 256>>>(wqk, wv);
    k_buckets <<<(BH * T_ + 255) / 256, 256>>>(rot);
    k_sort    <<<BH * NH, T_>>>();
    k_attn    <<<dim3(80, 128), 256, ATTN_SMEM>>>();
    k_combine <<<BH * T_ / 8, 256>>>();
    k_gemm_out<<<dim3(4, 160), 256>>>(wout, bout, out);
}